// round 1
// baseline (speedup 1.0000x reference)
#include <cuda_runtime.h>
#include <math.h>

#define N 8192
#define C 128
#define TM 128
#define TN 128
#define BK 16
#define SPAD 132   // padded smem row length (floats) to soften STS bank conflicts

// Scratch (device globals: allocation-free rule)
__device__ float  g_nA[N * C];   // l2-normalized img, scaled by sqrt(10)
__device__ float  g_nB[N * C];   // l2-normalized mol, scaled by sqrt(10)
__device__ double g_sumlog;      // sum over all 4*N rows of log(sum_{j!=i} exp(s_ij - 10))
__device__ double g_sumd;        // sum_i 10*dot(img_i, mol_i)

__global__ void init_kernel() {
    g_sumlog = 0.0;
    g_sumd   = 0.0;
}

// One block (128 threads) per row; blockIdx.y selects img/mol.
__global__ void norm_kernel(const float* __restrict__ img,
                            const float* __restrict__ mol) {
    const int row = blockIdx.x;
    const float* src = blockIdx.y ? mol : img;
    float* dst       = blockIdx.y ? g_nB : g_nA;
    const int t = threadIdx.x;

    float v = src[row * C + t];
    float s = v * v;
    #pragma unroll
    for (int m = 16; m > 0; m >>= 1) s += __shfl_xor_sync(0xffffffffu, s, m);

    __shared__ float red[4];
    if ((t & 31) == 0) red[t >> 5] = s;
    __syncthreads();
    s = red[0] + red[1] + red[2] + red[3];

    float nrm = fmaxf(sqrtf(s), 1e-12f);          // matches F.normalize eps
    dst[row * C + t] = v * (3.16227766016837933f / nrm);   // * sqrt(10) -> logits directly
}

// blockIdx.z selects the pass: 0:(A,B)+diag  1:(B,A)  2:(A,A)  3:(B,B)
// Each block owns TM=128 rows, streams all N columns in TN=128 tiles,
// accumulates per-row sum_{j!=i} exp(s_ij - 10), then adds sum of logs.
__global__ __launch_bounds__(256, 2) void pass_kernel() {
    __shared__ float Xs[BK * SPAD];
    __shared__ float Ys[BK * SPAD];
    __shared__ float rowsum[TM];
    __shared__ float redblk[8];

    const int z = blockIdx.z;
    const float* __restrict__ X;
    const float* __restrict__ Y;
    if      (z == 0) { X = g_nA; Y = g_nB; }
    else if (z == 1) { X = g_nB; Y = g_nA; }
    else if (z == 2) { X = g_nA; Y = g_nA; }
    else             { X = g_nB; Y = g_nB; }

    const int tid = threadIdx.x;
    const int tx  = tid & 15;
    const int ty  = tid >> 4;
    const int rowBase = blockIdx.x * TM;

    if (tid < TM) rowsum[tid] = 0.0f;

    float acc[8][8];

    for (int jt = 0; jt < N / TN; ++jt) {
        const int colBase = jt * TN;

        #pragma unroll
        for (int u = 0; u < 8; ++u)
            #pragma unroll
            for (int v = 0; v < 8; ++v) acc[u][v] = 0.0f;

        for (int kc = 0; kc < C; kc += BK) {
            __syncthreads();   // protect prior reads of Xs/Ys (and rowsum init on iter 0)
            // Load BK x 128 chunk of X rows and Y rows, transposed into smem [k][row].
            #pragma unroll
            for (int l = 0; l < 2; ++l) {
                const int id = tid + l * 256;     // 0..511
                const int r  = id >> 2;           // 0..127
                const int kq = id & 3;            // float4 slot within chunk
                const float4 xv = *(const float4*)&X[(rowBase + r) * C + kc + kq * 4];
                const float4 yv = *(const float4*)&Y[(colBase + r) * C + kc + kq * 4];
                Xs[(kq * 4 + 0) * SPAD + r] = xv.x;
                Xs[(kq * 4 + 1) * SPAD + r] = xv.y;
                Xs[(kq * 4 + 2) * SPAD + r] = xv.z;
                Xs[(kq * 4 + 3) * SPAD + r] = xv.w;
                Ys[(kq * 4 + 0) * SPAD + r] = yv.x;
                Ys[(kq * 4 + 1) * SPAD + r] = yv.y;
                Ys[(kq * 4 + 2) * SPAD + r] = yv.z;
                Ys[(kq * 4 + 3) * SPAD + r] = yv.w;
            }
            __syncthreads();

            #pragma unroll
            for (int kk = 0; kk < BK; ++kk) {
                const float4 a0 = *(const float4*)&Xs[kk * SPAD + ty * 4];
                const float4 a1 = *(const float4*)&Xs[kk * SPAD + 64 + ty * 4];
                const float4 b0 = *(const float4*)&Ys[kk * SPAD + tx * 4];
                const float4 b1 = *(const float4*)&Ys[kk * SPAD + 64 + tx * 4];
                const float a[8] = {a0.x, a0.y, a0.z, a0.w, a1.x, a1.y, a1.z, a1.w};
                const float b[8] = {b0.x, b0.y, b0.z, b0.w, b1.x, b1.y, b1.z, b1.w};
                #pragma unroll
                for (int u = 0; u < 8; ++u)
                    #pragma unroll
                    for (int v = 0; v < 8; ++v)
                        acc[u][v] = fmaf(a[u], b[v], acc[u][v]);
            }
        }

        // Epilogue for this column tile: exp + row partial sums.
        #pragma unroll
        for (int u = 0; u < 8; ++u) {
            const int r  = ty * 4 + (u & 3) + (u >> 2) * 64;
            const int gi = rowBase + r;
            float rs = 0.0f;
            #pragma unroll
            for (int v = 0; v < 8; ++v) {
                const int gj = colBase + tx * 4 + (v & 3) + (v >> 2) * 64;
                const float d = acc[u][v];       // already 10*dot (inputs pre-scaled)
                if (gi == gj) {
                    if (z == 0) atomicAdd(&g_sumd, (double)d);
                    // diagonal excluded from every LSE
                } else {
                    rs += __expf(d - 10.0f);
                }
            }
            // reduce across the 16 tx lanes (stays within a half-warp)
            #pragma unroll
            for (int m = 8; m > 0; m >>= 1)
                rs += __shfl_xor_sync(0xffffffffu, rs, m);
            if (tx == 0) rowsum[r] += rs;        // unique writer per row
        }
    }

    __syncthreads();
    // Sum log(rowsum) over the 128 rows of this block.
    float l = (tid < TM) ? logf(rowsum[tid]) : 0.0f;
    #pragma unroll
    for (int m = 16; m > 0; m >>= 1) l += __shfl_xor_sync(0xffffffffu, l, m);
    if ((tid & 31) == 0) redblk[tid >> 5] = l;
    __syncthreads();
    if (tid == 0) {
        float bs = 0.0f;
        #pragma unroll
        for (int w = 0; w < 8; ++w) bs += redblk[w];
        atomicAdd(&g_sumlog, (double)bs);
    }
}

__global__ void finalize_kernel(float* __restrict__ out) {
    // loss = -(1/N) * sum(10*d_i) + 20 + (0.5/N) * sum(all 4N logs)
    const double invN = 1.0 / (double)N;
    out[0] = (float)(-g_sumd * invN + 20.0 + 0.5 * g_sumlog * invN);
}

extern "C" void kernel_launch(void* const* d_in, const int* in_sizes, int n_in,
                              void* d_out, int out_size) {
    const float* img = (const float*)d_in[0];
    const float* mol = (const float*)d_in[1];
    float* out = (float*)d_out;

    init_kernel<<<1, 1>>>();
    norm_kernel<<<dim3(N, 2), C>>>(img, mol);
    pass_kernel<<<dim3(N / TM, 1, 4), 256>>>();
    finalize_kernel<<<1, 1>>>(out);
}

// round 4
// speedup vs baseline: 8.2040x; 8.2040x over previous
#include <cuda_runtime.h>
#include <cuda_fp16.h>
#include <math.h>
#include <cstdint>

#define NN 8192
#define NROW 16384
#define CC 128
#define NTILES 8256            // 128*129/2 upper-triangular stripe pairs
#define PITCH 136              // halves per smem row (272 B, 16B-aligned, bank-staggered)
#define STRIPE_BYTES (128 * PITCH * 2)   // 34816
#define SMEM_TOTAL (4 * STRIPE_BYTES)    // X0 X1 Y0 Y1 = 139264

// ---- device scratch (allocation-free rule) ----
__device__ __align__(16) __half g_Z[NROW * CC];  // normalized * sqrt(10), f16 row-major
__device__ float   g_rowS[NROW];       // per-row sum exp(s-10), same-modality cols
__device__ float   g_rowX[NROW];       // per-row sum exp(s-10), cross-modality cols
__device__ double  g_sumlog;
__device__ double  g_sumd;

// ---- PTX helpers (base sm_80+ features only) ----
__device__ __forceinline__ uint32_t smem_u32(const void* p) {
    uint32_t a;
    asm("{ .reg .u64 t; cvta.to.shared.u64 t, %1; cvt.u32.u64 %0, t; }" : "=r"(a) : "l"(p));
    return a;
}
__device__ __forceinline__ float ex2f(float x) {
    float y; asm("ex2.approx.f32 %0, %1;" : "=f"(y) : "f"(x)); return y;
}
__device__ __forceinline__ void cp16(uint32_t dst, const void* src) {
    asm volatile("cp.async.cg.shared.global [%0], [%1], 16;" :: "r"(dst), "l"(src));
}
#define CP_COMMIT() asm volatile("cp.async.commit_group;" ::: "memory")
#define CP_WAIT(n)  asm volatile("cp.async.wait_group %0;" :: "n"(n) : "memory")

__device__ __forceinline__ void ldsm4(uint32_t* r, uint32_t addr) {
    asm volatile("ldmatrix.sync.aligned.m8n8.x4.shared.b16 {%0,%1,%2,%3}, [%4];"
                 : "=r"(r[0]), "=r"(r[1]), "=r"(r[2]), "=r"(r[3]) : "r"(addr));
}
__device__ __forceinline__ void mma16816(float* d, const uint32_t* a, uint32_t b0, uint32_t b1) {
    asm volatile(
        "mma.sync.aligned.m16n8k16.row.col.f32.f16.f16.f32 "
        "{%0,%1,%2,%3}, {%4,%5,%6,%7}, {%8,%9}, {%0,%1,%2,%3};"
        : "+f"(d[0]), "+f"(d[1]), "+f"(d[2]), "+f"(d[3])
        : "r"(a[0]), "r"(a[1]), "r"(a[2]), "r"(a[3]), "r"(b0), "r"(b1));
}

// linear upper-tri index t -> (i, j), i <= j, base(i) = i*(257-i)/2
__device__ __forceinline__ void t2ij(int t, int& i, int& j) {
    int ii = (int)((257.0f - sqrtf(66049.0f - 8.0f * (float)t)) * 0.5f);
    if (ii < 0) ii = 0;
    while (ii > 0 && ii * (257 - ii) / 2 > t) --ii;
    while ((ii + 1) * (256 - ii) / 2 <= t) ++ii;
    i = ii;
    j = ii + (t - ii * (257 - ii) / 2);
}

// ---------------------------------------------------------------------------
__global__ void init_kernel() {
    const int t = blockIdx.x * blockDim.x + threadIdx.x;
    if (t < NROW) { g_rowS[t] = 0.0f; g_rowX[t] = 0.0f; }
    if (t == 0) { g_sumlog = 0.0; g_sumd = 0.0; }
}

// One 128-thread block per global row. Normalize, scale by sqrt(10), f16.
__global__ void norm_kernel(const float* __restrict__ img,
                            const float* __restrict__ mol) {
    const int gr = blockIdx.x;
    const float* src = (gr < NN) ? (img + (size_t)gr * CC) : (mol + (size_t)(gr - NN) * CC);
    const int t = threadIdx.x;

    float v = src[t];
    float s = v * v;
    #pragma unroll
    for (int m = 16; m > 0; m >>= 1) s += __shfl_xor_sync(0xffffffffu, s, m);
    __shared__ float red[4];
    if ((t & 31) == 0) red[t >> 5] = s;
    __syncthreads();
    s = red[0] + red[1] + red[2] + red[3];

    const float scale = 3.16227766016837933f / fmaxf(sqrtf(s), 1e-12f);
    g_Z[(size_t)gr * CC + t] = __float2half(v * scale);
}

// ---------------------------------------------------------------------------
// Upper-triangular Gram: persistent CTAs, each 256 threads (8 warps, 2x4),
// CTA tile 128x128, warp tile 64x32, double-buffered cp.async stripes.
__global__ __launch_bounds__(256, 1) void gram_kernel() {
    extern __shared__ __align__(256) unsigned char smem[];
    const uint32_t sb = smem_u32(smem);
    const int tid = threadIdx.x;
    const int wid = tid >> 5, lane = tid & 31;
    const int wm = wid >> 2, wn = wid & 3;

    // ldmatrix per-lane base coordinates
    const int a_row = wm * 64 + (lane & 15);
    const int a_k   = (lane >> 4) * 8;
    const int b_row = wn * 32 + (lane & 7) + ((lane >> 4) << 3);
    const int b_k   = ((lane >> 3) & 1) * 8;

    auto load_stripe = [&](int stripe, uint32_t dstoff) {
        const __half* src = g_Z + (size_t)stripe * 128 * CC;
        #pragma unroll
        for (int l = 0; l < 8; ++l) {            // 2048 x 16B = full 32KB stripe
            const int idx = tid + l * 256;        // 0..2047
            const int row = idx >> 4, c = idx & 15;
            cp16(sb + dstoff + (uint32_t)(row * PITCH + c * 8) * 2,
                 src + row * CC + c * 8);
        }
    };

    {   // prologue: load first tile's stripes into buffer 0
        int i0, j0; t2ij(blockIdx.x, i0, j0);
        load_stripe(i0, 0);
        load_stripe(j0, 2 * STRIPE_BYTES);
        CP_COMMIT();
    }

    int n = 0;
    for (int t = blockIdx.x; t < NTILES; t += gridDim.x, ++n) {
        int i, j; t2ij(t, i, j);

        const int tn = t + gridDim.x;
        if (tn < NTILES) {
            int i2, j2; t2ij(tn, i2, j2);
            const uint32_t nb = (uint32_t)((n + 1) & 1);
            load_stripe(i2, nb * STRIPE_BYTES);
            load_stripe(j2, (2 + nb) * STRIPE_BYTES);
            CP_COMMIT();
            CP_WAIT(1);
        } else {
            CP_WAIT(0);
        }
        __syncthreads();

        const uint32_t cb = (uint32_t)(n & 1);
        const uint32_t xs = sb + cb * STRIPE_BYTES;
        const uint32_t ys = sb + (2 + cb) * STRIPE_BYTES;

        float acc[4][4][4];
        #pragma unroll
        for (int mf = 0; mf < 4; ++mf)
            #pragma unroll
            for (int nf = 0; nf < 4; ++nf)
                #pragma unroll
                for (int e = 0; e < 4; ++e) acc[mf][nf][e] = 0.0f;

        #pragma unroll
        for (int ks = 0; ks < 8; ++ks) {
            uint32_t a[4][4], b[2][4];
            #pragma unroll
            for (int mf = 0; mf < 4; ++mf)
                ldsm4(a[mf], xs + (uint32_t)((a_row + mf * 16) * PITCH + a_k + ks * 16) * 2);
            #pragma unroll
            for (int nfp = 0; nfp < 2; ++nfp)
                ldsm4(b[nfp], ys + (uint32_t)((b_row + nfp * 16) * PITCH + b_k + ks * 16) * 2);
            #pragma unroll
            for (int mf = 0; mf < 4; ++mf)
                #pragma unroll
                for (int nf = 0; nf < 4; ++nf)
                    mma16816(acc[mf][nf], a[mf], b[nf >> 1][(nf & 1) * 2], b[nf >> 1][(nf & 1) * 2 + 1]);
        }

        // ---- epilogue: exp(s-10), masked diagonals, row + col partial sums
        const bool dmask = (i == j);
        const bool xmask = (j == i + 64);
        float sd = 0.0f;
        float rowp[4][2], colp[4][2];
        #pragma unroll
        for (int q = 0; q < 4; ++q) { rowp[q][0] = rowp[q][1] = 0.0f; colp[q][0] = colp[q][1] = 0.0f; }

        #pragma unroll
        for (int mf = 0; mf < 4; ++mf)
            #pragma unroll
            for (int nf = 0; nf < 4; ++nf)
                #pragma unroll
                for (int e = 0; e < 4; ++e) {
                    const float s = acc[mf][nf][e];
                    float ex = ex2f(fmaf(s, 1.4426950408889634f, -14.426950408889634f));
                    if (dmask | xmask) {
                        const int rl = wm * 64 + mf * 16 + (lane >> 2) + ((e >> 1) << 3);
                        const int cl = wn * 32 + nf * 8 + ((lane & 3) << 1) + (e & 1);
                        if (rl == cl) { sd += s; ex = 0.0f; }
                    }
                    rowp[mf][e >> 1] += ex;
                    colp[nf][e & 1]  += ex;
                }

        float* dst = ((i < 64) == (j < 64)) ? g_rowS : g_rowX;

        #pragma unroll
        for (int mf = 0; mf < 4; ++mf)
            #pragma unroll
            for (int h = 0; h < 2; ++h) {
                float v = rowp[mf][h];
                v += __shfl_xor_sync(0xffffffffu, v, 1);
                v += __shfl_xor_sync(0xffffffffu, v, 2);
                if ((lane & 3) == 0)
                    atomicAdd(&dst[i * 128 + wm * 64 + mf * 16 + (lane >> 2) + h * 8], v);
            }

        if (i != j) {   // symmetric contribution: column sums feed stripe j rows
            #pragma unroll
            for (int nf = 0; nf < 4; ++nf)
                #pragma unroll
                for (int h = 0; h < 2; ++h) {
                    float v = colp[nf][h];
                    v += __shfl_xor_sync(0xffffffffu, v, 4);
                    v += __shfl_xor_sync(0xffffffffu, v, 8);
                    v += __shfl_xor_sync(0xffffffffu, v, 16);
                    if (lane < 4)
                        atomicAdd(&dst[j * 128 + wn * 32 + nf * 8 + (lane << 1) + h], v);
                }
        }

        if (xmask) {    // positive-pair logits on this tile's diagonal
            #pragma unroll
            for (int m = 16; m > 0; m >>= 1) sd += __shfl_xor_sync(0xffffffffu, sd, m);
            if (lane == 0) atomicAdd(&g_sumd, (double)sd);
        }
        __syncthreads();
    }
}

// ---------------------------------------------------------------------------
__global__ void logsum_kernel() {
    const int r = blockIdx.x * 256 + threadIdx.x;   // 64 x 256 = 16384
    float l = logf(g_rowS[r]) + logf(g_rowX[r]);
    #pragma unroll
    for (int m = 16; m > 0; m >>= 1) l += __shfl_xor_sync(0xffffffffu, l, m);
    __shared__ float red[8];
    if ((threadIdx.x & 31) == 0) red[threadIdx.x >> 5] = l;
    __syncthreads();
    if (threadIdx.x == 0) {
        float bs = 0.0f;
        #pragma unroll
        for (int w = 0; w < 8; ++w) bs += red[w];
        atomicAdd(&g_sumlog, (double)bs);
    }
}

__global__ void finalize_kernel(float* __restrict__ out) {
    const double invN = 1.0 / (double)NN;
    out[0] = (float)(-g_sumd * invN + 20.0 + 0.5 * g_sumlog * invN);
}

// ---------------------------------------------------------------------------
extern "C" void kernel_launch(void* const* d_in, const int* in_sizes, int n_in,
                              void* d_out, int out_size) {
    const float* img = (const float*)d_in[0];
    const float* mol = (const float*)d_in[1];
    float* out = (float*)d_out;

    cudaFuncSetAttribute(gram_kernel, cudaFuncAttributeMaxDynamicSharedMemorySize, SMEM_TOTAL);

    init_kernel<<<64, 256>>>();
    norm_kernel<<<NROW, CC>>>(img, mol);
    gram_kernel<<<148, 256, SMEM_TOTAL>>>();
    logsum_kernel<<<64, 256>>>();
    finalize_kernel<<<1, 1>>>(out);
}